// round 3
// baseline (speedup 1.0000x reference)
#include <cuda_runtime.h>
#include <cuda_fp16.h>
#include <math.h>
#include <stdint.h>

// Fixed problem shape: B=16 channels, T=2^20 samples, 48 kHz.
constexpr int T_LEN  = 1 << 20;
constexpr int BCH    = 16;
constexpr int CHUNK  = 8192;              // samples produced per serial worker
constexpr int WARM   = 24576;             // warm-up prefix (contraction kills init error)
constexpr int PER_CH = T_LEN / CHUNK;     // 128 chunks per channel
constexpr int NWORK  = BCH * PER_CH;      // 2048 serial workers (64 warps)
constexpr int SBT    = CHUNK / 4;         // float4 rows in transposed g scratch

// Scratch 1: per-sample packed (alpha_att*gr, alpha_rel*gr) as half2 (4 B/sample, 64 MB).
__device__ __half2 d_pg[(size_t)BCH * T_LEN + 256];
// Scratch 2: smoothed envelope, worker-transposed: d_gt[s/4][w] float4 (64 MB).
__device__ float4 d_gt[(size_t)SBT * NWORK];

__device__ __forceinline__ float f_lg2(float x) {
    float r; asm("lg2.approx.f32 %0, %1;" : "=f"(r) : "f"(x)); return r;
}
__device__ __forceinline__ float f_ex2(float x) {
    float r; asm("ex2.approx.ftz.f32 %0, %1;" : "=f"(r) : "f"(x)); return r;
}
// Branch-free envelope step: g' = max(ba*g + pa, br*g + pr).
// Selects the attack affine map exactly when gr >= g (alpha_att > alpha_rel).
__device__ __forceinline__ float stepg(float g, __half2 h, float ba, float br) {
    float2 p = __half22float2(h);
    return fmaxf(fmaf(ba, g, p.x), fmaf(br, g, p.y));
}

// ---------------------------------------------------------------------------
// Pass 1: elementwise gain computer.
//   gr = max( (20*log10(|a|+1e-8) - thr) * (1 - 1/ratio), 0 )
// stored as half2(alpha_att*gr, alpha_rel*gr).
// ---------------------------------------------------------------------------
__global__ void __launch_bounds__(256)
pg_kernel(const float* __restrict__ audio,
          const float* __restrict__ p_thr,
          const float* __restrict__ p_ratio,
          const float* __restrict__ p_att,
          const float* __restrict__ p_rel,
          int n4)
{
    int i = blockIdx.x * blockDim.x + threadIdx.x;
    if (i >= n4) return;

    const float R    = 1.0f - 1.0f / (*p_ratio);
    const float kl   = 6.0205999132796239f * R;   // 20*log10(2) * R
    const float kc   = -(*p_thr) * R;
    const float aatt = 1.0f - expf(-1.0f / ((*p_att) * 48000.0f));
    const float arel = 1.0f - expf(-1.0f / ((*p_rel) * 48000.0f));

    float4 a = reinterpret_cast<const float4*>(audio)[i];
    float g0 = fmaxf(fmaf(kl, f_lg2(fabsf(a.x) + 1e-8f), kc), 0.0f);
    float g1 = fmaxf(fmaf(kl, f_lg2(fabsf(a.y) + 1e-8f), kc), 0.0f);
    float g2 = fmaxf(fmaf(kl, f_lg2(fabsf(a.z) + 1e-8f), kc), 0.0f);
    float g3 = fmaxf(fmaf(kl, f_lg2(fabsf(a.w) + 1e-8f), kc), 0.0f);

    union { __half2 h[4]; uint4 u; } o;
    o.h[0] = __floats2half2_rn(aatt * g0, arel * g0);
    o.h[1] = __floats2half2_rn(aatt * g1, arel * g1);
    o.h[2] = __floats2half2_rn(aatt * g2, arel * g2);
    o.h[3] = __floats2half2_rn(aatt * g3, arel * g3);
    reinterpret_cast<uint4*>(d_pg)[i] = o.u;
}

// ---------------------------------------------------------------------------
// Pass 2: chunked serial envelope scan. 2048 workers (64 warps, ~1/SM).
// Reads d_pg (per-lane streams 32KB apart), writes the envelope
// lane-coalesced (transposed) into d_gt.
// ---------------------------------------------------------------------------
__global__ void __launch_bounds__(32)
scan_kernel(const float* __restrict__ p_att,
            const float* __restrict__ p_rel)
{
    const int w = blockIdx.x * 32 + threadIdx.x;
    const int b = w >> 7;         // channel  (PER_CH = 128)
    const int j = w & 127;        // chunk within channel

    const __half2* PG = d_pg + (size_t)b * T_LEN;
    const float ba = expf(-1.0f / ((*p_att) * 48000.0f));   // 1 - alpha_attack
    const float br = expf(-1.0f / ((*p_rel) * 48000.0f));   // 1 - alpha_release

    const int t0 = j * CHUNK;
    float g = 0.0f;

    // ---------------- warm-up (recurrence only) ----------------
    int t = t0 - WARM;
    if (t < 1) t = 1;             // j <= 2: start from the true beginning (exact)
    while (t < t0 && (t & 15)) { g = stepg(g, PG[t], ba, br); ++t; }
    for (; t < t0; t += 16) {
        asm volatile("prefetch.global.L1 [%0];" :: "l"(PG + t + 160));
        union { uint4 u[4]; __half2 h[16]; } blk;
        const uint4* pv = reinterpret_cast<const uint4*>(PG + t);
#pragma unroll
        for (int q = 0; q < 4; ++q) blk.u[q] = pv[q];
#pragma unroll
        for (int k = 0; k < 16; ++k) g = stepg(g, blk.h[k], ba, br);
    }

    // ---------------- chunk (recurrence + transposed g store) ----------------
    int s = 0;
    if (j == 0) {
        // Sample 0: g[0] = 0 by definition (no step applied).
        float4 gb;
        gb.x = 0.0f;
        g = stepg(g, PG[1], ba, br); gb.y = g;
        g = stepg(g, PG[2], ba, br); gb.z = g;
        g = stepg(g, PG[3], ba, br); gb.w = g;
        d_gt[(size_t)0 * NWORK + w] = gb;
        for (int sb = 1; sb < 4; ++sb) {
            g = stepg(g, PG[4 * sb + 0], ba, br); gb.x = g;
            g = stepg(g, PG[4 * sb + 1], ba, br); gb.y = g;
            g = stepg(g, PG[4 * sb + 2], ba, br); gb.z = g;
            g = stepg(g, PG[4 * sb + 3], ba, br); gb.w = g;
            d_gt[(size_t)sb * NWORK + w] = gb;
        }
        s = 16;
    }
    for (; s < CHUNK; s += 16) {
        const int tt = t0 + s;
        asm volatile("prefetch.global.L1 [%0];" :: "l"(PG + tt + 160));
        union { uint4 u[4]; __half2 h[16]; } blk;
        const uint4* pv = reinterpret_cast<const uint4*>(PG + tt);
#pragma unroll
        for (int q = 0; q < 4; ++q) blk.u[q] = pv[q];

        float4 gb;
#pragma unroll
        for (int q = 0; q < 4; ++q) {
            g = stepg(g, blk.h[4 * q + 0], ba, br); gb.x = g;
            g = stepg(g, blk.h[4 * q + 1], ba, br); gb.y = g;
            g = stepg(g, blk.h[4 * q + 2], ba, br); gb.z = g;
            g = stepg(g, blk.h[4 * q + 3], ba, br); gb.w = g;
            d_gt[(size_t)((s >> 2) + q) * NWORK + w] = gb;   // coalesced across lanes
        }
    }
}

// ---------------------------------------------------------------------------
// Pass 3: tiled un-transpose of the envelope + output gain application.
//   out = audio * 2^( -K*g + K*makeup ),  K = log2(10)/20
// ---------------------------------------------------------------------------
__global__ void __launch_bounds__(256)
out_kernel(const float* __restrict__ audio,
           const float* __restrict__ p_mk,
           float* __restrict__ out)
{
    __shared__ float tile[32][33];
    const int tx  = threadIdx.x;           // 0..31
    const int ty  = threadIdx.y;           // 0..7
    const int sb0 = blockIdx.x * 8;        // 8 float4 rows = 32 samples
    const int s0  = blockIdx.x * 32;
    const int w0  = blockIdx.y * 32;

    float4 v = d_gt[(size_t)(sb0 + ty) * NWORK + (w0 + tx)];
    tile[ty * 4 + 0][tx] = v.x;
    tile[ty * 4 + 1][tx] = v.y;
    tile[ty * 4 + 2][tx] = v.z;
    tile[ty * 4 + 3][tx] = v.w;
    __syncthreads();

    const float K  = 0.16609640474436813f;  // log2(10)/20
    const float c3 = -K;
    const float c4 = (*p_mk) * K;

#pragma unroll
    for (int r = 0; r < 4; ++r) {
        const int wl = r * 8 + ty;
        const int w  = w0 + wl;
        const int b  = w >> 7;
        const int j  = w & 127;
        const size_t idx = (size_t)b * T_LEN + (size_t)j * CHUNK + s0 + tx;
        out[idx] = audio[idx] * f_ex2(fmaf(c3, tile[tx][wl], c4));
    }
}

// Fallback for unexpected shapes: plain single-thread-per-channel scan (slow
// but correct) — only used if n != BCH*T_LEN, which setup_inputs never does.
__global__ void fallback_kernel(const float* __restrict__ audio,
                                const float* __restrict__ p_thr,
                                const float* __restrict__ p_ratio,
                                const float* __restrict__ p_att,
                                const float* __restrict__ p_rel,
                                const float* __restrict__ p_mk,
                                float* __restrict__ out, int Bn, int Tn)
{
    int c = blockIdx.x * blockDim.x + threadIdx.x;
    if (c >= Bn) return;
    const float R  = 1.0f - 1.0f / (*p_ratio);
    const float aa = 1.0f - expf(-1.0f / ((*p_att) * 48000.0f));
    const float ar = 1.0f - expf(-1.0f / ((*p_rel) * 48000.0f));
    const float K  = 0.16609640474436813f;
    float g = 0.0f;
    for (int t = 0; t < Tn; ++t) {
        float a  = audio[(size_t)c * Tn + t];
        float gr = fmaxf((20.0f * log10f(fabsf(a) + 1e-8f) - *p_thr) * R, 0.0f);
        if (t > 0) { float al = gr > g ? aa : ar; g = (1.0f - al) * g + al * gr; }
        out[(size_t)c * Tn + t] = a * f_ex2(fmaf(-K, g, (*p_mk) * K));
    }
}

extern "C" void kernel_launch(void* const* d_in, const int* in_sizes, int n_in,
                              void* d_out, int out_size)
{
    const float* audio   = (const float*)d_in[0];
    const float* thr     = (const float*)d_in[1];
    const float* ratio   = (const float*)d_in[2];
    const float* attack  = (const float*)d_in[3];
    const float* release = (const float*)d_in[4];
    const float* makeup  = (const float*)d_in[5];
    float* out = (float*)d_out;

    const int n = in_sizes[0];
    if (n == BCH * T_LEN) {
        const int n4 = n / 4;
        pg_kernel<<<(n4 + 255) / 256, 256>>>(audio, thr, ratio, attack, release, n4);
        scan_kernel<<<NWORK / 32, 32>>>(attack, release);
        out_kernel<<<dim3(SBT / 8, NWORK / 32), dim3(32, 8)>>>(audio, makeup, out);
    } else {
        fallback_kernel<<<1, 32>>>(audio, thr, ratio, attack, release, makeup,
                                   out, BCH, n / BCH);
    }
}

// round 4
// speedup vs baseline: 2.5775x; 2.5775x over previous
#include <cuda_runtime.h>
#include <math.h>
#include <stdint.h>

// Fixed problem shape: B=16 channels, T=2^20 samples, 48 kHz.
constexpr int T_LEN   = 1 << 20;
constexpr int BCH     = 16;
constexpr int CHUNK   = 4096;               // samples produced per serial worker
constexpr int WARM_CH = 5;                  // warm-up chunks (20480 samples)
constexpr int PER_CH  = T_LEN / CHUNK;      // 256 chunks per channel
constexpr int NWORK   = BCH * PER_CH;       // 4096 serial workers (128 warps)
constexpr int ROWS    = CHUNK / 4;          // 1024 float4 rows per chunk column
constexpr int PAD_R   = 32;                 // slack rows for pipelined over-read

// Scratch 1: gain-reduction gr, worker-transposed. pg_t[row][worker] where
// row r holds samples 4r..4r+3 of that worker's chunk. (~69 MB)
__device__ float4 d_pgT[(size_t)(ROWS + PAD_R) * NWORK];
// Scratch 2: smoothed envelope g, same transposed layout. (64 MB)
__device__ float4 d_gt[(size_t)ROWS * NWORK];

__device__ __forceinline__ float f_lg2(float x) {
    float r; asm("lg2.approx.f32 %0, %1;" : "=f"(r) : "f"(x)); return r;
}
__device__ __forceinline__ float f_ex2(float x) {
    float r; asm("ex2.approx.ftz.f32 %0, %1;" : "=f"(r) : "f"(x)); return r;
}

// ---------------------------------------------------------------------------
// Pass 1: gain computer + transpose.
//   gr = max( (20*log10(|a|+1e-8) - thr) * (1 - 1/ratio), 0 )
// Reads audio coalesced, writes d_pgT coalesced via an smem tile.
// ---------------------------------------------------------------------------
__global__ void __launch_bounds__(256)
pg_kernel(const float* __restrict__ audio,
          const float* __restrict__ p_thr,
          const float* __restrict__ p_ratio)
{
    __shared__ float4 tile[8][33];
    const int tid = threadIdx.x;
    const int r0  = blockIdx.x * 8;       // float4-row tile origin
    const int w0  = blockIdx.y * 32;      // worker tile origin

    const float R  = 1.0f - 1.0f / (*p_ratio);
    const float kl = 6.0205999132796239f * R;   // 20*log10(2) * R
    const float kc = -(*p_thr) * R;

    // Phase A: coalesced audio reads (8 threads = one 128B line per worker).
    {
        const int wl   = tid >> 3;        // 0..31 worker within tile
        const int rowk = tid & 7;         // 0..7  row within tile
        const int w = w0 + wl;
        const int b = w >> 8;             // channel  (PER_CH = 256)
        const int j = w & 255;            // chunk within channel
        const size_t aidx = (size_t)b * T_LEN + (size_t)j * CHUNK
                          + (size_t)(r0 + rowk) * 4;
        float4 a = *reinterpret_cast<const float4*>(audio + aidx);
        float4 gr;
        gr.x = fmaxf(fmaf(kl, f_lg2(fabsf(a.x) + 1e-8f), kc), 0.0f);
        gr.y = fmaxf(fmaf(kl, f_lg2(fabsf(a.y) + 1e-8f), kc), 0.0f);
        gr.z = fmaxf(fmaf(kl, f_lg2(fabsf(a.z) + 1e-8f), kc), 0.0f);
        gr.w = fmaxf(fmaf(kl, f_lg2(fabsf(a.w) + 1e-8f), kc), 0.0f);
        tile[rowk][wl] = gr;
    }
    __syncthreads();

    // Phase B: coalesced transposed writes (one row of 32 float4 per warp).
    {
        const int rowk = tid >> 5;        // 0..7
        const int wl   = tid & 31;        // 0..31
        d_pgT[(size_t)(r0 + rowk) * NWORK + (w0 + wl)] = tile[rowk][wl];
    }
}

// ---------------------------------------------------------------------------
// Pass 2: chunked serial envelope scan, quad-buffered registers.
// One lane per worker; all global traffic coalesced across the warp.
// Branch-free step: g' = max(ba*g + aatt*gr, br*g + arel*gr) — selects the
// attack map exactly when gr >= g (aatt > arel).
// ---------------------------------------------------------------------------
template<bool STORE>
__device__ __forceinline__ void run_phase(const float4* __restrict__ cp,
                                          float4* __restrict__ gp,
                                          float& g,
                                          float aatt, float arel,
                                          float ba, float br)
{
    float4 S[4][4];
    // Preload stages for iterations 0, 1, 2 (rows 0..11).
#pragma unroll
    for (int n = 0; n < 3; ++n)
#pragma unroll
        for (int k = 0; k < 4; ++k)
            S[n][k] = cp[(size_t)(n * 4 + k) * NWORK];

#pragma unroll 1
    for (int it = 0; it < ROWS / 4; it += 4) {
        const float4* p = cp + (size_t)it * 4 * NWORK;
        float4*       q = gp + (size_t)it * 4 * NWORK;
#pragma unroll
        for (int u = 0; u < 4; ++u) {
            // Issue loads for iteration it+u+3 (3 iterations ahead).
#pragma unroll
            for (int k = 0; k < 4; ++k)
                S[(u + 3) & 3][k] = p[(size_t)((u + 3) * 4 + k) * NWORK];
            // Serial chain for iteration it+u (16 samples).
#pragma unroll
            for (int k = 0; k < 4; ++k) {
                float4 v = S[u][k];
                float4 gb;
                g = fmaxf(fmaf(ba, g, aatt * v.x), fmaf(br, g, arel * v.x)); gb.x = g;
                g = fmaxf(fmaf(ba, g, aatt * v.y), fmaf(br, g, arel * v.y)); gb.y = g;
                g = fmaxf(fmaf(ba, g, aatt * v.z), fmaf(br, g, arel * v.z)); gb.z = g;
                g = fmaxf(fmaf(ba, g, aatt * v.w), fmaf(br, g, arel * v.w)); gb.w = g;
                if constexpr (STORE)
                    q[(size_t)(u * 4 + k) * NWORK] = gb;
            }
        }
    }
}

__global__ void __launch_bounds__(32)
scan_kernel(const float* __restrict__ p_att,
            const float* __restrict__ p_rel)
{
    const int w = blockIdx.x * 32 + threadIdx.x;
    const int j = w & 255;                      // chunk within channel

    const float ba   = expf(-1.0f / ((*p_att) * 48000.0f));  // 1 - alpha_attack
    const float br   = expf(-1.0f / ((*p_rel) * 48000.0f));  // 1 - alpha_release
    const float aatt = 1.0f - ba;
    const float arel = 1.0f - br;

    float g = 0.0f;
    float4* gp = d_gt + w;

    // Warm-up: 5 chunks of preceding samples (columns w-5+i). Lanes whose
    // warm-up would cross their channel start read garbage there and are
    // reset to the exact initial state g=0 at their channel-start phase.
#pragma unroll 1
    for (int i = 0; i < WARM_CH; ++i) {
        if (WARM_CH - j == i) g = 0.0f;
        int c = w - WARM_CH + i;
        if (c < 0) c = 0;
        run_phase<false>(d_pgT + c, gp, g, aatt, arel, ba, br);
    }
    if (j == 0) g = 0.0f;                       // channel starts here: exact
    run_phase<true>(d_pgT + w, gp, g, aatt, arel, ba, br);
}

// ---------------------------------------------------------------------------
// Pass 3: tiled un-transpose of the envelope + output gain.
//   out = audio * 2^( -K*g + K*makeup ),  K = log2(10)/20
// ---------------------------------------------------------------------------
__global__ void __launch_bounds__(256)
out_kernel(const float* __restrict__ audio,
           const float* __restrict__ p_mk,
           float* __restrict__ out)
{
    __shared__ float tile[32][33];
    const int tx  = threadIdx.x;           // 0..31
    const int ty  = threadIdx.y;           // 0..7
    const int sb0 = blockIdx.x * 8;        // 8 float4 rows = 32 samples
    const int s0  = blockIdx.x * 32;
    const int w0  = blockIdx.y * 32;

    float4 v = d_gt[(size_t)(sb0 + ty) * NWORK + (w0 + tx)];
    tile[ty * 4 + 0][tx] = v.x;
    tile[ty * 4 + 1][tx] = v.y;
    tile[ty * 4 + 2][tx] = v.z;
    tile[ty * 4 + 3][tx] = v.w;
    __syncthreads();

    const float K  = 0.16609640474436813f;  // log2(10)/20
    const float c3 = -K;
    const float c4 = (*p_mk) * K;

#pragma unroll
    for (int r = 0; r < 4; ++r) {
        const int wl = r * 8 + ty;
        const int w  = w0 + wl;
        const int b  = w >> 8;
        const int j  = w & 255;
        const size_t idx = (size_t)b * T_LEN + (size_t)j * CHUNK + s0 + tx;
        out[idx] = audio[idx] * f_ex2(fmaf(c3, tile[tx][wl], c4));
    }
}

// Fallback for unexpected shapes (never taken for this dataset).
__global__ void fallback_kernel(const float* __restrict__ audio,
                                const float* __restrict__ p_thr,
                                const float* __restrict__ p_ratio,
                                const float* __restrict__ p_att,
                                const float* __restrict__ p_rel,
                                const float* __restrict__ p_mk,
                                float* __restrict__ out, int Bn, int Tn)
{
    int c = blockIdx.x * blockDim.x + threadIdx.x;
    if (c >= Bn) return;
    const float R  = 1.0f - 1.0f / (*p_ratio);
    const float aa = 1.0f - expf(-1.0f / ((*p_att) * 48000.0f));
    const float ar = 1.0f - expf(-1.0f / ((*p_rel) * 48000.0f));
    const float K  = 0.16609640474436813f;
    float g = 0.0f;
    for (int t = 0; t < Tn; ++t) {
        float a  = audio[(size_t)c * Tn + t];
        float gr = fmaxf((20.0f * log10f(fabsf(a) + 1e-8f) - *p_thr) * R, 0.0f);
        if (t > 0) { float al = gr > g ? aa : ar; g = (1.0f - al) * g + al * gr; }
        out[(size_t)c * Tn + t] = a * f_ex2(fmaf(-K, g, (*p_mk) * K));
    }
}

extern "C" void kernel_launch(void* const* d_in, const int* in_sizes, int n_in,
                              void* d_out, int out_size)
{
    const float* audio   = (const float*)d_in[0];
    const float* thr     = (const float*)d_in[1];
    const float* ratio   = (const float*)d_in[2];
    const float* attack  = (const float*)d_in[3];
    const float* release = (const float*)d_in[4];
    const float* makeup  = (const float*)d_in[5];
    float* out = (float*)d_out;

    const int n = in_sizes[0];
    if (n == BCH * T_LEN) {
        pg_kernel<<<dim3(ROWS / 8, NWORK / 32), 256>>>(audio, thr, ratio);
        scan_kernel<<<NWORK / 32, 32>>>(attack, release);
        out_kernel<<<dim3(ROWS / 8, NWORK / 32), dim3(32, 8)>>>(audio, makeup, out);
    } else {
        fallback_kernel<<<1, 32>>>(audio, thr, ratio, attack, release, makeup,
                                   out, BCH, n / BCH);
    }
}

// round 5
// speedup vs baseline: 3.4706x; 1.3465x over previous
#include <cuda_runtime.h>
#include <math.h>
#include <stdint.h>

// Fixed problem shape: B=16 channels, T=2^20 samples, 48 kHz.
constexpr int T_LEN   = 1 << 20;
constexpr int BCH     = 16;
constexpr int CHUNK   = 2048;               // samples produced per serial worker
constexpr int WARM_CH = 9;                  // warm-up chunks (18432 samples)
constexpr int PER_CH  = T_LEN / CHUNK;      // 512 chunks per channel
constexpr int NWORK   = BCH * PER_CH;       // 8192 serial workers (256 warps)
constexpr int ROWS    = CHUNK / 4;          // 512 float4 rows per chunk column
constexpr int PAD_R   = 32;                 // slack rows for pipelined over-read

// Scratch 1: gain-reduction gr, worker-transposed: d_pgT[row][worker], row r
// holds samples 4r..4r+3 of that worker's chunk. 64 MB -> fits in L2 (126 MB).
__device__ float4 d_pgT[(size_t)(ROWS + PAD_R) * NWORK];
// Scratch 2: smoothed envelope g, same layout. Written/read with .cs hints so
// it does not evict d_pgT from L2.
__device__ float4 d_gt[(size_t)ROWS * NWORK];

__device__ __forceinline__ float f_lg2(float x) {
    float r; asm("lg2.approx.f32 %0, %1;" : "=f"(r) : "f"(x)); return r;
}
__device__ __forceinline__ float f_ex2(float x) {
    float r; asm("ex2.approx.ftz.f32 %0, %1;" : "=f"(r) : "f"(x)); return r;
}

// ---------------------------------------------------------------------------
// Pass 1: gain computer + transpose.
//   gr = max( (20*log10(|a|+1e-8) - thr) * (1 - 1/ratio), 0 )
// Reads audio coalesced, writes d_pgT coalesced via an smem tile.
// ---------------------------------------------------------------------------
__global__ void __launch_bounds__(256)
pg_kernel(const float* __restrict__ audio,
          const float* __restrict__ p_thr,
          const float* __restrict__ p_ratio)
{
    __shared__ float4 tile[8][33];
    const int tid = threadIdx.x;
    const int r0  = blockIdx.x * 8;       // float4-row tile origin
    const int w0  = blockIdx.y * 32;      // worker tile origin

    const float R  = 1.0f - 1.0f / (*p_ratio);
    const float kl = 6.0205999132796239f * R;   // 20*log10(2) * R
    const float kc = -(*p_thr) * R;

    // Phase A: coalesced audio reads (8 threads cover one worker's 8 rows).
    {
        const int wl   = tid >> 3;        // 0..31 worker within tile
        const int rowk = tid & 7;         // 0..7  row within tile
        const int w = w0 + wl;
        const int b = w >> 9;             // channel  (PER_CH = 512)
        const int j = w & 511;            // chunk within channel
        const size_t aidx = (size_t)b * T_LEN + (size_t)j * CHUNK
                          + (size_t)(r0 + rowk) * 4;
        float4 a = *reinterpret_cast<const float4*>(audio + aidx);
        float4 gr;
        gr.x = fmaxf(fmaf(kl, f_lg2(fabsf(a.x) + 1e-8f), kc), 0.0f);
        gr.y = fmaxf(fmaf(kl, f_lg2(fabsf(a.y) + 1e-8f), kc), 0.0f);
        gr.z = fmaxf(fmaf(kl, f_lg2(fabsf(a.z) + 1e-8f), kc), 0.0f);
        gr.w = fmaxf(fmaf(kl, f_lg2(fabsf(a.w) + 1e-8f), kc), 0.0f);
        tile[rowk][wl] = gr;
    }
    __syncthreads();

    // Phase B: coalesced transposed writes.
    {
        const int rowk = tid >> 5;        // 0..7
        const int wl   = tid & 31;        // 0..31
        d_pgT[(size_t)(r0 + rowk) * NWORK + (w0 + wl)] = tile[rowk][wl];
    }
}

// ---------------------------------------------------------------------------
// Pass 2: chunked serial envelope scan, quad-buffered registers.
// Branch-free step: g' = max(ba*g + aatt*gr, br*g + arel*gr) — selects the
// attack map exactly when gr >= g (aatt > arel).
// ---------------------------------------------------------------------------
template<bool STORE>
__device__ __forceinline__ void run_phase(const float4* __restrict__ cp,
                                          float4* __restrict__ gp,
                                          float& g,
                                          float aatt, float arel,
                                          float ba, float br)
{
    float4 S[4][4];
    // Preload stages for iterations 0, 1, 2 (rows 0..11).
#pragma unroll
    for (int n = 0; n < 3; ++n)
#pragma unroll
        for (int k = 0; k < 4; ++k)
            S[n][k] = cp[(size_t)(n * 4 + k) * NWORK];

#pragma unroll 1
    for (int it = 0; it < ROWS / 4; it += 4) {
        const float4* p = cp + (size_t)it * 4 * NWORK;
        float4*       q = gp + (size_t)it * 4 * NWORK;
#pragma unroll
        for (int u = 0; u < 4; ++u) {
            // Issue loads for iteration it+u+3 (3 iterations ~ 570 cyc ahead).
#pragma unroll
            for (int k = 0; k < 4; ++k)
                S[(u + 3) & 3][k] = p[(size_t)((u + 3) * 4 + k) * NWORK];
            // Serial chain for iteration it+u (16 samples).
#pragma unroll
            for (int k = 0; k < 4; ++k) {
                float4 v = S[u][k];
                float4 gb;
                g = fmaxf(fmaf(ba, g, aatt * v.x), fmaf(br, g, arel * v.x)); gb.x = g;
                g = fmaxf(fmaf(ba, g, aatt * v.y), fmaf(br, g, arel * v.y)); gb.y = g;
                g = fmaxf(fmaf(ba, g, aatt * v.z), fmaf(br, g, arel * v.z)); gb.z = g;
                g = fmaxf(fmaf(ba, g, aatt * v.w), fmaf(br, g, arel * v.w)); gb.w = g;
                if constexpr (STORE)
                    __stcs(&q[(size_t)(u * 4 + k) * NWORK], gb);  // evict-first
            }
        }
    }
}

__global__ void __launch_bounds__(32)
scan_kernel(const float* __restrict__ p_att,
            const float* __restrict__ p_rel)
{
    const int w = blockIdx.x * 32 + threadIdx.x;
    const int j = w & 511;                      // chunk within channel

    const float ba   = expf(-1.0f / ((*p_att) * 48000.0f));  // 1 - alpha_attack
    const float br   = expf(-1.0f / ((*p_rel) * 48000.0f));  // 1 - alpha_release
    const float aatt = 1.0f - ba;
    const float arel = 1.0f - br;

    float g = 0.0f;
    float4* gp = d_gt + w;

    // Warm-up: 9 preceding chunk-columns. Lanes whose warm-up would cross
    // their channel start are reset to the exact initial state g=0 at the
    // phase where the true channel start lies (earlier phases read junk but
    // are erased by the reset).
#pragma unroll 1
    for (int i = 0; i < WARM_CH; ++i) {
        if (WARM_CH - j == i) g = 0.0f;
        int c = w - WARM_CH + i;
        if (c < 0) c = 0;
        run_phase<false>(d_pgT + c, gp, g, aatt, arel, ba, br);
    }
    if (j == 0) g = 0.0f;                       // channel starts here: exact
    run_phase<true>(d_pgT + w, gp, g, aatt, arel, ba, br);
}

// ---------------------------------------------------------------------------
// Pass 3: tiled un-transpose of the envelope + output gain.
//   out = audio * 2^( -K*g + K*makeup ),  K = log2(10)/20
// ---------------------------------------------------------------------------
__global__ void __launch_bounds__(256)
out_kernel(const float* __restrict__ audio,
           const float* __restrict__ p_mk,
           float* __restrict__ out)
{
    __shared__ float tile[32][33];
    const int tx  = threadIdx.x;           // 0..31
    const int ty  = threadIdx.y;           // 0..7
    const int sb0 = blockIdx.x * 8;        // 8 float4 rows = 32 samples
    const int s0  = blockIdx.x * 32;
    const int w0  = blockIdx.y * 32;

    float4 v = __ldcs(&d_gt[(size_t)(sb0 + ty) * NWORK + (w0 + tx)]);
    tile[ty * 4 + 0][tx] = v.x;
    tile[ty * 4 + 1][tx] = v.y;
    tile[ty * 4 + 2][tx] = v.z;
    tile[ty * 4 + 3][tx] = v.w;
    __syncthreads();

    const float K  = 0.16609640474436813f;  // log2(10)/20
    const float c3 = -K;
    const float c4 = (*p_mk) * K;

#pragma unroll
    for (int r = 0; r < 4; ++r) {
        const int wl = r * 8 + ty;
        const int w  = w0 + wl;
        const int b  = w >> 9;
        const int j  = w & 511;
        const size_t idx = (size_t)b * T_LEN + (size_t)j * CHUNK + s0 + tx;
        out[idx] = audio[idx] * f_ex2(fmaf(c3, tile[tx][wl], c4));
    }
}

// Fallback for unexpected shapes (never taken for this dataset).
__global__ void fallback_kernel(const float* __restrict__ audio,
                                const float* __restrict__ p_thr,
                                const float* __restrict__ p_ratio,
                                const float* __restrict__ p_att,
                                const float* __restrict__ p_rel,
                                const float* __restrict__ p_mk,
                                float* __restrict__ out, int Bn, int Tn)
{
    int c = blockIdx.x * blockDim.x + threadIdx.x;
    if (c >= Bn) return;
    const float R  = 1.0f - 1.0f / (*p_ratio);
    const float aa = 1.0f - expf(-1.0f / ((*p_att) * 48000.0f));
    const float ar = 1.0f - expf(-1.0f / ((*p_rel) * 48000.0f));
    const float K  = 0.16609640474436813f;
    float g = 0.0f;
    for (int t = 0; t < Tn; ++t) {
        float a  = audio[(size_t)c * Tn + t];
        float gr = fmaxf((20.0f * log10f(fabsf(a) + 1e-8f) - *p_thr) * R, 0.0f);
        if (t > 0) { float al = gr > g ? aa : ar; g = (1.0f - al) * g + al * gr; }
        out[(size_t)c * Tn + t] = a * f_ex2(fmaf(-K, g, (*p_mk) * K));
    }
}

extern "C" void kernel_launch(void* const* d_in, const int* in_sizes, int n_in,
                              void* d_out, int out_size)
{
    const float* audio   = (const float*)d_in[0];
    const float* thr     = (const float*)d_in[1];
    const float* ratio   = (const float*)d_in[2];
    const float* attack  = (const float*)d_in[3];
    const float* release = (const float*)d_in[4];
    const float* makeup  = (const float*)d_in[5];
    float* out = (float*)d_out;

    const int n = in_sizes[0];
    if (n == BCH * T_LEN) {
        pg_kernel<<<dim3(ROWS / 8, NWORK / 32), 256>>>(audio, thr, ratio);
        scan_kernel<<<NWORK / 32, 32>>>(attack, release);
        out_kernel<<<dim3(ROWS / 8, NWORK / 32), dim3(32, 8)>>>(audio, makeup, out);
    } else {
        fallback_kernel<<<1, 32>>>(audio, thr, ratio, attack, release, makeup,
                                   out, BCH, n / BCH);
    }
}